// round 16
// baseline (speedup 1.0000x reference)
#include <cuda_runtime.h>

// ---------------------------------------------------------------------------
// OscillatorBank — XLA ReduceWindowRewriter(base_length=16) bit-replication.
// (Scheme confirmed R11; perf rounds since.) Phase path bit-identical.
//   f0:[8,500,1] loudness:[8,500,1] harm_amps:[8,500,60] -> signal:[8,128000]
// ---------------------------------------------------------------------------

#define BB    8
#define TT    500
#define NH    60
#define LL    128000
#define SEQN  (BB * NH)     // 480 (b,h) sequences
#define B16   16
#define N1    8000          // LL/16
#define N2    500           // N1/16

__device__ float g_z  [BB * TT * NH];  // fl(fl(f0*k)*CSC), layout [b][frame][h]
__device__ float g_am [BB * TT * NH];  // masked amps,      layout [b][frame][h]
__device__ float g_B1 [SEQN * N1];     // level-1 block sums
__device__ float g_B2 [SEQN * N2];     // level-2 block sums
__device__ float g_R2 [SEQN * N1];     // corrected level-2 values [seq][m]
__device__ float g_R2T[BB * N1 * NH];  // transposed: [b][m][h]

__device__ __forceinline__ float RPOS() { return __fdiv_rn(499.0f, 127999.0f); }
__device__ __forceinline__ float CSC()  { return (float)(6.283185307179586 / 16000.0); }
__device__ __forceinline__ float TPIF() { return (float)6.283185307179586; }

__device__ __forceinline__ float interp1(float a, float b, float w) {
    return __fadd_rn(__fmul_rn(a, __fsub_rn(1.0f, w)), __fmul_rn(b, w));
}

// Exact fmodf(x, fl32(2*pi)) for x >= 0 (bit-identical to jnp.mod for x>=0).
__device__ __forceinline__ float exact_mod_2pi(float x) {
    const float y = TPIF();
    float q = truncf(__fmul_rn(x, 0.15915494f));
    float r = __fmaf_rn(-q, y, x);
    if (r < 0.0f)     r = __fmaf_rn(-(q - 1.0f), y, x);
    else if (r >= y)  r = __fmaf_rn(-(q + 1.0f), y, x);
    return r;
}

// ---------------------------------------------------------------------------
// KZ: precompute z and masked-amp tables (bit-identical values). 240k threads.
// ---------------------------------------------------------------------------
__global__ void k_z(const float* __restrict__ f0, const float* __restrict__ amps) {
    int idx = blockIdx.x * blockDim.x + threadIdx.x;   // (b*500+i)*60+h
    if (idx >= BB * TT * NH) return;
    int h  = idx % NH;
    int bi = idx / NH;
    float f  = __ldg(f0 + bi);
    float kf = (float)(h + 1);
    float fk = __fmul_rn(f, kf);
    g_z[idx]  = __fmul_rn(fk, CSC());
    g_am[idx] = (fk > 8000.0f) ? 0.0f : __ldg(amps + idx);
}

// ---------------------------------------------------------------------------
// K1: level-1 block sums (16 leaves, strict left-to-right) + fused level-2
// sums via half-warp shuffles. A 16-block spans <=2 frames: z loads hoisted.
// grid 15000 x 256.
// ---------------------------------------------------------------------------
__global__ void __launch_bounds__(256) k_b1(void) {
    int gw   = blockIdx.x * 8 + (threadIdx.x >> 5);
    int lane = threadIdx.x & 31;
    int seq  = gw / 250;
    int pr   = gw - seq * 250;
    int row  = pr * 2 + (lane >> 4);                   // [0,500)
    int m    = row * B16 + (lane & 15);                // [0,8000)
    int b = seq / NH, h = seq - b * NH;
    float rpos = RPOS();
    const float* zb = g_z + (size_t)b * TT * NH + h;

    int l0 = m * B16;
    float posf = __fmul_rn((float)l0, rpos);
    int i0f = (int)posf; if (i0f > TT - 2) i0f = TT - 2;
    float posl = __fmul_rn((float)(l0 + 15), rpos);
    int i0l = (int)posl; if (i0l > TT - 2) i0l = TT - 2;
    float zf0 = __ldg(zb + i0f * NH), zf1 = __ldg(zb + (i0f + 1) * NH);
    float zl0 = __ldg(zb + i0l * NH), zl1 = __ldg(zb + (i0l + 1) * NH);
    float fi0f = (float)i0f, fi0l = (float)i0l;

    float p = 0.0f, lf = (float)l0;
    #pragma unroll
    for (int j = 0; j < B16; j++) {
        float pos = __fmul_rn(lf, rpos);
        int i0 = (int)pos; if (i0 > TT - 2) i0 = TT - 2;
        bool sec = (i0 > i0f);
        float fi0 = sec ? fi0l : fi0f;
        float z0  = sec ? zl0  : zf0;
        float z1  = sec ? zl1  : zf1;
        float w   = __fsub_rn(pos, fi0);
        float omw = __fsub_rn(1.0f, w);
        p  = __fadd_rn(p, __fadd_rn(__fmul_rn(z0, omw), __fmul_rn(z1, w)));
        lf = __fadd_rn(lf, 1.0f);                      // exact (< 2^24)
    }
    g_B1[seq * N1 + m] = p;

    // B2[row] = sequential left-to-right sum of the 16 lane values
    int base = (lane & 16);
    float s = 0.0f;
    #pragma unroll
    for (int j = 0; j < B16; j++)
        s = __fadd_rn(s, __shfl_sync(0xffffffffu, p, base + j));
    if ((lane & 15) == 0)
        g_B2[seq * N2 + row] = s;
}

// ---------------------------------------------------------------------------
// K2: fused levels 3..5 (warp 0 -> smem R3) + corrected level-2 R2[8000].
// CTA per seq, smem-staged with stride-17 padding. grid 480 x 512.
// ---------------------------------------------------------------------------
__global__ void __launch_bounds__(512) k_r2(void) {
    int seq = blockIdx.x;
    int tid = threadIdx.x;
    __shared__ float sb[8500];                         // 8000 + row pads
    __shared__ float sR3[N2];

    const float* B1 = g_B1 + seq * N1;
    for (int q = tid; q < N1; q += 512)
        sb[q + (q >> 4)] = B1[q];

    if (tid < 32) {                                    // warp 0: R3[500]
        int lane = tid;
        const float* B2 = g_B2 + seq * N2;
        float b3 = 0.0f;                               // level-3 block sums
        for (int j = 0; j < B16; j++) {
            int k = lane * B16 + j;
            if (k >= N2) break;
            b3 = __fadd_rn(b3, B2[k]);
        }
        int hb = lane & 16;                            // level-4 prefixes
        float p4 = 0.0f;
        #pragma unroll
        for (int j = 0; j < B16; j++) {
            float t = __shfl_sync(0xffffffffu, b3, hb + j);
            if (j <= (lane & 15)) p4 = __fadd_rn(p4, t);
        }
        float b40 = __shfl_sync(0xffffffffu, p4, 15);  // naive scan(2)
        float r4  = (lane < 16) ? p4 : __fadd_rn(p4, b40);
        float off = __shfl_up_sync(0xffffffffu, r4, 1);
        float p = 0.0f;                                // corrected R3
        for (int j = 0; j < B16; j++) {
            int k = lane * B16 + j;
            if (k >= N2) break;
            p = __fadd_rn(p, B2[k]);
            sR3[k] = (lane > 0) ? __fadd_rn(p, off) : p;
        }
    }
    __syncthreads();

    if (tid < N2) {                                    // corrected R2 rows
        int r = tid;
        float off = (r > 0) ? sR3[r - 1] : 0.0f;
        int sbase = r * 17;
        float p = 0.0f;
        #pragma unroll
        for (int j = 0; j < B16; j++) {
            p = __fadd_rn(p, sb[sbase + j]);
            sb[sbase + j] = (r > 0) ? __fadd_rn(p, off) : p;  // fl(p+0)=p
        }
    }
    __syncthreads();

    float* R2 = g_R2 + seq * N1;
    for (int q = tid; q < N1; q += 512)
        R2[q] = sb[q + (q >> 4)];
}

// ---------------------------------------------------------------------------
// KT: transpose R2 [seq][m] -> R2T [b][m][h]. 80x60 tiles, float4 loads,
// pad-85 smem (conflict-free), coalesced flat stores. grid (100, 8) x 256.
// ---------------------------------------------------------------------------
__global__ void __launch_bounds__(256) k_tr(void) {
    int b  = blockIdx.y;
    int m0 = blockIdx.x * 80;
    __shared__ float tile[NH * 85];                    // [h][mm], pad 85

    // load: 60 rows x 20 float4 (80 consecutive m per row)
    for (int idx = threadIdx.x; idx < NH * 20; idx += 256) {
        int h = idx / 20, q4 = idx - h * 20;
        const float4* src = reinterpret_cast<const float4*>(
            &g_R2[(size_t)(b * NH + h) * N1 + m0 + q4 * 4]);
        float4 v = __ldg(src);
        int base = h * 85 + q4 * 4;
        tile[base]     = v.x;
        tile[base + 1] = v.y;
        tile[base + 2] = v.z;
        tile[base + 3] = v.w;
    }
    __syncthreads();

    // store: flat = mm*60+h, contiguous in R2T
    float* dst = g_R2T + ((size_t)b * N1 + m0) * NH;
    for (int idx = threadIdx.x; idx < 80 * NH; idx += 256) {
        int mm = idx / NH, h = idx - mm * NH;
        dst[idx] = tile[h * 85 + mm];
    }
}

// ---------------------------------------------------------------------------
// K3: fused final. grid (2000, 8) x 256 = 4 slots x 64 threads.
// Per slot, 16 threads precompute float4(w, 1-w, sec) for the 16 j's (shared
// by all 60 h-threads). Straddle (<=1 frame boundary, slot-uniform) splits a
// no-select fast path from a select path where zl0==zf1, al0==af1.
// S = fl(P1 + off) (off coalesced from R2T; 0.0 exact for m==0), exact mod,
// __sinf, amp interp -> smem; 4x15 partials + 16-thread combine + loudness.
// ---------------------------------------------------------------------------
__global__ void __launch_bounds__(256) k_osc(const float* __restrict__ loud,
                                             float* __restrict__ out) {
    int slot = threadIdx.x >> 6;
    int h    = threadIdx.x & 63;
    int m    = blockIdx.x * 4 + slot;                  // [0, 8000)
    int b    = blockIdx.y;
    float rpos = RPOS();
    int l0 = m * B16;

    __shared__ float4 sws[4][B16];
    __shared__ float  shp[4 * NH * 17];
    __shared__ float  aux[4 * 64];

    if (h < B16) {                                     // per-j shared tables
        int t = l0 + h;
        float pos = __fmul_rn((float)t, rpos);
        int i0 = (int)pos; if (i0 > TT - 2) i0 = TT - 2;
        float posf = __fmul_rn((float)l0, rpos);
        int i0f = (int)posf; if (i0f > TT - 2) i0f = TT - 2;
        float w = __fsub_rn(pos, (float)i0);
        sws[slot][h] = make_float4(w, __fsub_rn(1.0f, w),
                                   (i0 > i0f) ? 1.0f : 0.0f, 0.0f);
    }
    __syncthreads();

    if (h < NH) {
        float posf = __fmul_rn((float)l0, rpos);
        int i0f = (int)posf; if (i0f > TT - 2) i0f = TT - 2;
        float posl = __fmul_rn((float)(l0 + 15), rpos);
        int i0l = (int)posl; if (i0l > TT - 2) i0l = TT - 2;

        const float* amb = g_am + (size_t)b * TT * NH + h;
        float af0 = __ldg(amb + i0f * NH);
        float af1 = __ldg(amb + (i0f + 1) * NH);
        float al1 = __ldg(amb + (i0l + 1) * NH);

        float* shrow = shp + (slot * NH + h) * 17;
        if ((af0 == 0.0f) & (af1 == 0.0f) & (al1 == 0.0f)) {
            #pragma unroll
            for (int j = 0; j < B16; j++) shrow[j] = 0.0f;   // exact +-0 terms
        } else {
            const float* zb = g_z + (size_t)b * TT * NH + h;
            float zf0 = __ldg(zb + i0f * NH), zf1 = __ldg(zb + (i0f + 1) * NH);
            float off = (m > 0)
                ? __ldg(&g_R2T[((size_t)b * N1 + m - 1) * NH + h]) : 0.0f;
            float p = 0.0f;

            if (i0l == i0f) {                          // slot-uniform fast path
                #pragma unroll
                for (int j = 0; j < B16; j++) {
                    float4 ws = sws[slot][j];
                    p = __fadd_rn(p, __fadd_rn(__fmul_rn(zf0, ws.y),
                                               __fmul_rn(zf1, ws.x)));
                    float S  = __fadd_rn(p, off);      // off=0 exact for m==0
                    float sn = __sinf(exact_mod_2pi(S));
                    float av = __fadd_rn(__fmul_rn(af0, ws.y),
                                         __fmul_rn(af1, ws.x));
                    shrow[j] = __fmul_rn(av, sn);
                }
            } else {                                   // straddle: i0l = i0f+1
                float zl1 = __ldg(zb + (i0l + 1) * NH);
                #pragma unroll
                for (int j = 0; j < B16; j++) {
                    float4 ws = sws[slot][j];
                    bool sec = (ws.z != 0.0f);
                    float z0 = sec ? zf1 : zf0;        // zl0 == zf1
                    float z1 = sec ? zl1 : zf1;
                    float a0 = sec ? af1 : af0;        // al0 == af1
                    float a1 = sec ? al1 : af1;
                    p = __fadd_rn(p, __fadd_rn(__fmul_rn(z0, ws.y),
                                               __fmul_rn(z1, ws.x)));
                    float S  = __fadd_rn(p, off);
                    float sn = __sinf(exact_mod_2pi(S));
                    float av = __fadd_rn(__fmul_rn(a0, ws.y),
                                         __fmul_rn(a1, ws.x));
                    shrow[j] = __fmul_rn(av, sn);
                }
            }
        }
    }
    __syncthreads();

    {   // 4 groups x 15 rows partial sums (sum order is output-level freedom)
        int g = h >> 4, c = h & 15;
        const float* base = shp + (slot * NH + g * 15) * 17 + c;
        float s = 0.0f;
        #pragma unroll
        for (int r = 0; r < 15; r++)
            s = __fadd_rn(s, base[r * 17]);
        aux[slot * 64 + h] = s;
    }
    __syncthreads();

    if (h < B16) {
        int t = l0 + h;
        float pos = __fmul_rn((float)t, rpos);
        int i0 = (int)pos; if (i0 > TT - 2) i0 = TT - 2;
        float w  = __fsub_rn(pos, (float)i0);
        const float* ldb = loud + b * TT;
        float lv = interp1(__ldg(ldb + i0), __ldg(ldb + i0 + 1), w);
        const float* a = aux + slot * 64 + h;
        float acc = __fadd_rn(__fadd_rn(a[0], a[16]), __fadd_rn(a[32], a[48]));
        out[(size_t)b * LL + t] = __fmul_rn(lv, acc);
    }
}

// ---------------------------------------------------------------------------
extern "C" void kernel_launch(void* const* d_in, const int* in_sizes, int n_in,
                              void* d_out, int out_size) {
    const float* f0   = (const float*)d_in[0];   // [8,500,1]
    const float* loud = (const float*)d_in[1];   // [8,500,1]
    const float* amps = (const float*)d_in[2];   // [8,500,60]
    float* out = (float*)d_out;                  // [8,128000]
    (void)in_sizes; (void)n_in; (void)out_size;

    k_z<<<(BB * TT * NH + 255) / 256, 256>>>(f0, amps);
    k_b1<<<15000, 256>>>();
    k_r2<<<SEQN, 512>>>();
    dim3 gt(N1 / 80, BB);
    k_tr<<<gt, 256>>>();
    dim3 g3(N1 / 4, BB);
    k_osc<<<g3, 256>>>(loud, out);
}

// round 17
// speedup vs baseline: 1.0926x; 1.0926x over previous
#include <cuda_runtime.h>

// ---------------------------------------------------------------------------
// OscillatorBank — XLA ReduceWindowRewriter(base_length=16) bit-replication.
// (Scheme confirmed R11; perf rounds since.) Phase path bit-identical.
//   f0:[8,500,1] loudness:[8,500,1] harm_amps:[8,500,60] -> signal:[8,128000]
// ---------------------------------------------------------------------------

#define BB    8
#define TT    500
#define NH    60
#define LL    128000
#define SEQN  (BB * NH)     // 480 (b,h) sequences
#define B16   16
#define N1    8000          // LL/16
#define N2    500           // N1/16
#define RPC   8             // rows per CTA in k_r2t

__device__ float g_z  [BB * TT * NH];  // fl(fl(f0*k)*CSC), layout [b][frame][h]
__device__ float g_am [BB * TT * NH];  // masked amps,      layout [b][frame][h]
__device__ float g_B1 [SEQN * N1];     // level-1 block sums
__device__ float g_B2 [SEQN * N2];     // level-2 block sums
__device__ float g_R3 [SEQN * N2];     // corrected level-3 values
__device__ float g_R2T[BB * N1 * NH];  // corrected level-2, transposed [b][m][h]

__device__ __forceinline__ float RPOS() { return __fdiv_rn(499.0f, 127999.0f); }
__device__ __forceinline__ float CSC()  { return (float)(6.283185307179586 / 16000.0); }
__device__ __forceinline__ float TPIF() { return (float)6.283185307179586; }

__device__ __forceinline__ float interp1(float a, float b, float w) {
    return __fadd_rn(__fmul_rn(a, __fsub_rn(1.0f, w)), __fmul_rn(b, w));
}

// Exact fmodf(x, fl32(2*pi)) for x >= 0 (bit-identical to jnp.mod for x>=0).
__device__ __forceinline__ float exact_mod_2pi(float x) {
    const float y = TPIF();
    float q = truncf(__fmul_rn(x, 0.15915494f));
    float r = __fmaf_rn(-q, y, x);
    if (r < 0.0f)     r = __fmaf_rn(-(q - 1.0f), y, x);
    else if (r >= y)  r = __fmaf_rn(-(q + 1.0f), y, x);
    return r;
}

// ---------------------------------------------------------------------------
// KZ: precompute z and masked-amp tables (bit-identical values). 240k threads.
// ---------------------------------------------------------------------------
__global__ void k_z(const float* __restrict__ f0, const float* __restrict__ amps) {
    int idx = blockIdx.x * blockDim.x + threadIdx.x;   // (b*500+i)*60+h
    if (idx >= BB * TT * NH) return;
    int h  = idx % NH;
    int bi = idx / NH;
    float f  = __ldg(f0 + bi);
    float kf = (float)(h + 1);
    float fk = __fmul_rn(f, kf);
    g_z[idx]  = __fmul_rn(fk, CSC());
    g_am[idx] = (fk > 8000.0f) ? 0.0f : __ldg(amps + idx);
}

// ---------------------------------------------------------------------------
// K1: level-1 block sums (16 leaves, strict left-to-right) + fused level-2
// sums via half-warp shuffles. A 16-block spans <=2 frames: z loads hoisted.
// grid 15000 x 256.
// ---------------------------------------------------------------------------
__global__ void __launch_bounds__(256) k_b1(void) {
    int gw   = blockIdx.x * 8 + (threadIdx.x >> 5);
    int lane = threadIdx.x & 31;
    int seq  = gw / 250;
    int pr   = gw - seq * 250;
    int row  = pr * 2 + (lane >> 4);                   // [0,500)
    int m    = row * B16 + (lane & 15);                // [0,8000)
    int b = seq / NH, h = seq - b * NH;
    float rpos = RPOS();
    const float* zb = g_z + (size_t)b * TT * NH + h;

    int l0 = m * B16;
    float posf = __fmul_rn((float)l0, rpos);
    int i0f = (int)posf; if (i0f > TT - 2) i0f = TT - 2;
    float posl = __fmul_rn((float)(l0 + 15), rpos);
    int i0l = (int)posl; if (i0l > TT - 2) i0l = TT - 2;
    float zf0 = __ldg(zb + i0f * NH), zf1 = __ldg(zb + (i0f + 1) * NH);
    float zl0 = __ldg(zb + i0l * NH), zl1 = __ldg(zb + (i0l + 1) * NH);
    float fi0f = (float)i0f, fi0l = (float)i0l;

    float p = 0.0f, lf = (float)l0;
    #pragma unroll
    for (int j = 0; j < B16; j++) {
        float pos = __fmul_rn(lf, rpos);
        int i0 = (int)pos; if (i0 > TT - 2) i0 = TT - 2;
        bool sec = (i0 > i0f);
        float fi0 = sec ? fi0l : fi0f;
        float z0  = sec ? zl0  : zf0;
        float z1  = sec ? zl1  : zf1;
        float w   = __fsub_rn(pos, fi0);
        float omw = __fsub_rn(1.0f, w);
        p  = __fadd_rn(p, __fadd_rn(__fmul_rn(z0, omw), __fmul_rn(z1, w)));
        lf = __fadd_rn(lf, 1.0f);                      // exact (< 2^24)
    }
    g_B1[seq * N1 + m] = p;

    // B2[row] = sequential left-to-right sum of the 16 lane values
    int base = (lane & 16);
    float s = 0.0f;
    #pragma unroll
    for (int j = 0; j < B16; j++)
        s = __fadd_rn(s, __shfl_sync(0xffffffffu, p, base + j));
    if ((lane & 15) == 0)
        g_B2[seq * N2 + row] = s;
}

// ---------------------------------------------------------------------------
// K2a: levels 3..5 -> corrected R3[500] per seq. Warp per seq. grid 60 x 256.
// ---------------------------------------------------------------------------
__global__ void __launch_bounds__(256) k_r3(void) {
    int seq  = blockIdx.x * 8 + (threadIdx.x >> 5);
    int lane = threadIdx.x & 31;                       // level-3 row r = lane
    const float* B2 = g_B2 + seq * N2;
    float* R3 = g_R3 + seq * N2;

    float b3 = 0.0f;                                   // level-3 block sums
    for (int j = 0; j < B16; j++) {
        int k = lane * B16 + j;
        if (k >= N2) break;
        b3 = __fadd_rn(b3, B2[k]);
    }
    int hb = lane & 16;                                // level-4 prefixes
    float p4 = 0.0f;
    #pragma unroll
    for (int j = 0; j < B16; j++) {
        float t = __shfl_sync(0xffffffffu, b3, hb + j);
        if (j <= (lane & 15)) p4 = __fadd_rn(p4, t);
    }
    float b40 = __shfl_sync(0xffffffffu, p4, 15);      // naive scan(2)
    float r4  = (lane < 16) ? p4 : __fadd_rn(p4, b40);
    float off = __shfl_up_sync(0xffffffffu, r4, 1);
    float p = 0.0f;                                    // corrected R3
    for (int j = 0; j < B16; j++) {
        int k = lane * B16 + j;
        if (k >= N2) break;
        p = __fadd_rn(p, B2[k]);
        R3[k] = (lane > 0) ? __fadd_rn(p, off) : p;
    }
}

// ---------------------------------------------------------------------------
// K2b: corrected level-2 values, written DIRECTLY TRANSPOSED to R2T [b][m][h].
// CTA = (b, 8 rows) x 480 threads (60 h x 8 rows). float4-coalesced B1 loads,
// register chains, pad-129 smem stage, vectorized coalesced stores.
// grid (63, 8) x 480.
// ---------------------------------------------------------------------------
__global__ void __launch_bounds__(480) k_r2t(void) {
    int b  = blockIdx.y;
    int r0 = blockIdx.x * RPC;
    int tid = threadIdx.x;
    int h  = tid / RPC, rr = tid - (tid / RPC) * RPC;
    int r  = r0 + rr;
    __shared__ float tile[NH * 129];                   // [h][mm], pad 129

    if (r < N2) {
        float off = (r > 0) ? __ldg(&g_R3[(b * NH + h) * N2 + r - 1]) : 0.0f;
        const float4* src = reinterpret_cast<const float4*>(
            &g_B1[(size_t)(b * NH + h) * N1 + r * B16]);
        float4 v0 = __ldg(src), v1 = __ldg(src + 1);
        float4 v2 = __ldg(src + 2), v3 = __ldg(src + 3);
        float x[16] = {v0.x, v0.y, v0.z, v0.w, v1.x, v1.y, v1.z, v1.w,
                       v2.x, v2.y, v2.z, v2.w, v3.x, v3.y, v3.z, v3.w};
        float p = 0.0f;
        int tb = h * 129 + rr * B16;
        #pragma unroll
        for (int j = 0; j < B16; j++) {
            p = __fadd_rn(p, x[j]);
            tile[tb + j] = __fadd_rn(p, off);          // off=0 exact for r==0 (p>0)
        }
    }
    __syncthreads();

    int nrows = (N2 - r0 < RPC) ? (N2 - r0) : RPC;
    int total = nrows * B16 * NH;                      // multiple of 4
    float4* dst4 = reinterpret_cast<float4*>(
        g_R2T + ((size_t)b * N1 + r0 * B16) * NH);
    for (int q = tid; q * 4 < total; q += 480) {
        int f = q * 4;
        float4 v;
        v.x = tile[((f    ) % NH) * 129 + (f    ) / NH];
        v.y = tile[((f + 1) % NH) * 129 + (f + 1) / NH];
        v.z = tile[((f + 2) % NH) * 129 + (f + 2) / NH];
        v.w = tile[((f + 3) % NH) * 129 + (f + 3) / NH];
        dst4[q] = v;
    }
}

// ---------------------------------------------------------------------------
// K3: fused final, BLOCK PAIRS. grid (1000, 8) x 256 = 4 pairslots x 64 thr.
// Thread h runs TWO independent 16-chains (blocks m0, m0+1; <=1 frame
// boundary in 32 samples), interleaved for ILP; z/amp/mask/off amortized.
// S = fl(P1 + off) (off coalesced from R2T; 0.0 exact for m==0), exact mod,
// __sinf, amp interp -> smem; 2x30 partials + 32-thread combine + loudness.
// ---------------------------------------------------------------------------
__global__ void __launch_bounds__(256) k_osc(const float* __restrict__ loud,
                                             float* __restrict__ out) {
    int ps = threadIdx.x >> 6;
    int h  = threadIdx.x & 63;
    int mp = blockIdx.x * 4 + ps;                      // pair index [0,4000)
    int m0 = mp * 2;
    int b  = blockIdx.y;
    float rpos = RPOS();
    int l0 = m0 * B16;                                 // 32 samples

    __shared__ float4 sws[4][32];
    __shared__ float  shp[4 * NH * 33];
    __shared__ float  aux[4 * 64];

    float posf = __fmul_rn((float)l0, rpos);
    int i0f = (int)posf; if (i0f > TT - 2) i0f = TT - 2;

    if (h < 32) {                                      // per-j shared tables
        int t = l0 + h;
        float pos = __fmul_rn((float)t, rpos);
        int i0 = (int)pos; if (i0 > TT - 2) i0 = TT - 2;
        float w = __fsub_rn(pos, (float)i0);
        sws[ps][h] = make_float4(w, __fsub_rn(1.0f, w),
                                 (i0 > i0f) ? 1.0f : 0.0f, 0.0f);
    }
    __syncthreads();

    if (h < NH) {
        float posl = __fmul_rn((float)(l0 + 31), rpos);
        int i0l = (int)posl; if (i0l > TT - 2) i0l = TT - 2;

        const float* amb = g_am + (size_t)b * TT * NH + h;
        float af0 = __ldg(amb + i0f * NH);
        float af1 = __ldg(amb + (i0f + 1) * NH);
        float al1 = __ldg(amb + (i0l + 1) * NH);

        float* shrow = shp + (ps * NH + h) * 33;
        if ((af0 == 0.0f) & (af1 == 0.0f) & (al1 == 0.0f)) {
            #pragma unroll
            for (int j = 0; j < 32; j++) shrow[j] = 0.0f;    // exact +-0 terms
        } else {
            const float* zb = g_z + (size_t)b * TT * NH + h;
            float zf0 = __ldg(zb + i0f * NH), zf1 = __ldg(zb + (i0f + 1) * NH);
            const float* r2t = g_R2T + ((size_t)b * N1 + m0) * NH + h;
            float off0 = (m0 > 0) ? __ldg(r2t - NH) : 0.0f;  // R2[m0-1]
            float off1 = __ldg(r2t);                          // R2[m0]
            float p0 = 0.0f, p1 = 0.0f;

            if (i0l == i0f) {                          // slot-uniform fast path
                #pragma unroll
                for (int j = 0; j < B16; j++) {
                    float4 w0 = sws[ps][j];
                    float4 w1 = sws[ps][j + 16];
                    p0 = __fadd_rn(p0, __fadd_rn(__fmul_rn(zf0, w0.y),
                                                 __fmul_rn(zf1, w0.x)));
                    p1 = __fadd_rn(p1, __fadd_rn(__fmul_rn(zf0, w1.y),
                                                 __fmul_rn(zf1, w1.x)));
                    float S0 = __fadd_rn(p0, off0);    // off0=0 exact for m0==0
                    float S1 = __fadd_rn(p1, off1);
                    float sn0 = __sinf(exact_mod_2pi(S0));
                    float sn1 = __sinf(exact_mod_2pi(S1));
                    float av0 = __fadd_rn(__fmul_rn(af0, w0.y), __fmul_rn(af1, w0.x));
                    float av1 = __fadd_rn(__fmul_rn(af0, w1.y), __fmul_rn(af1, w1.x));
                    shrow[j]      = __fmul_rn(av0, sn0);
                    shrow[j + 16] = __fmul_rn(av1, sn1);
                }
            } else {                                   // straddle: i0l = i0f+1
                float zl1 = __ldg(zb + (i0l + 1) * NH);
                #pragma unroll
                for (int j = 0; j < B16; j++) {
                    float4 w0 = sws[ps][j];
                    float4 w1 = sws[ps][j + 16];
                    bool s0 = (w0.z != 0.0f), s1 = (w1.z != 0.0f);
                    float z00 = s0 ? zf1 : zf0, z01 = s0 ? zl1 : zf1;   // zl0==zf1
                    float z10 = s1 ? zf1 : zf0, z11 = s1 ? zl1 : zf1;
                    float a00 = s0 ? af1 : af0, a01 = s0 ? al1 : af1;   // al0==af1
                    float a10 = s1 ? af1 : af0, a11 = s1 ? al1 : af1;
                    p0 = __fadd_rn(p0, __fadd_rn(__fmul_rn(z00, w0.y),
                                                 __fmul_rn(z01, w0.x)));
                    p1 = __fadd_rn(p1, __fadd_rn(__fmul_rn(z10, w1.y),
                                                 __fmul_rn(z11, w1.x)));
                    float S0 = __fadd_rn(p0, off0);
                    float S1 = __fadd_rn(p1, off1);
                    float sn0 = __sinf(exact_mod_2pi(S0));
                    float sn1 = __sinf(exact_mod_2pi(S1));
                    float av0 = __fadd_rn(__fmul_rn(a00, w0.y), __fmul_rn(a01, w0.x));
                    float av1 = __fadd_rn(__fmul_rn(a10, w1.y), __fmul_rn(a11, w1.x));
                    shrow[j]      = __fmul_rn(av0, sn0);
                    shrow[j + 16] = __fmul_rn(av1, sn1);
                }
            }
        }
    }
    __syncthreads();

    {   // 2 groups x 30 rows partial sums (sum order is output-level freedom)
        int g = h >> 5, c = h & 31;
        const float* base = shp + (ps * NH + g * 30) * 33 + c;
        float s = 0.0f;
        #pragma unroll
        for (int r = 0; r < 30; r++)
            s = __fadd_rn(s, base[r * 33]);
        aux[ps * 64 + h] = s;
    }
    __syncthreads();

    if (h < 32) {
        int t = l0 + h;
        float pos = __fmul_rn((float)t, rpos);
        int i0 = (int)pos; if (i0 > TT - 2) i0 = TT - 2;
        float w  = __fsub_rn(pos, (float)i0);
        const float* ldb = loud + b * TT;
        float lv = interp1(__ldg(ldb + i0), __ldg(ldb + i0 + 1), w);
        float acc = __fadd_rn(aux[ps * 64 + h], aux[ps * 64 + 32 + h]);
        out[(size_t)b * LL + t] = __fmul_rn(lv, acc);
    }
}

// ---------------------------------------------------------------------------
extern "C" void kernel_launch(void* const* d_in, const int* in_sizes, int n_in,
                              void* d_out, int out_size) {
    const float* f0   = (const float*)d_in[0];   // [8,500,1]
    const float* loud = (const float*)d_in[1];   // [8,500,1]
    const float* amps = (const float*)d_in[2];   // [8,500,60]
    float* out = (float*)d_out;                  // [8,128000]
    (void)in_sizes; (void)n_in; (void)out_size;

    k_z<<<(BB * TT * NH + 255) / 256, 256>>>(f0, amps);
    k_b1<<<15000, 256>>>();
    k_r3<<<SEQN / 8, 256>>>();
    dim3 g2((N2 + RPC - 1) / RPC, BB);
    k_r2t<<<g2, 480>>>();
    dim3 g3(N1 / 8, BB);
    k_osc<<<g3, 256>>>(loud, out);
}